// round 1
// baseline (speedup 1.0000x reference)
#include <cuda_runtime.h>
#include <math.h>

// Problem constants
#define BATCH   2
#define SEQ     2048
#define HID     1024
#define NHEADS  16
#define HDIM    64
#define MTOT    (BATCH*SEQ)          // 4096 rows
#define QKV_N   (3*HID)              // 3072
#define LN_EPS  1e-5f

// -------- scratch (static device arrays; no allocation allowed) --------
__device__ float g_q [BATCH*NHEADS*SEQ*HDIM];   // [b,h,s,d] layernormed Q
__device__ float g_k [BATCH*NHEADS*SEQ*HDIM];   // [b,h,s,d] layernormed K
__device__ float g_v [BATCH*NHEADS*SEQ*HDIM];   // [b,h,s,d] V
__device__ float g_ao[BATCH*SEQ*HID];           // attention output, [b,s,h*d]

// ============================================================================
// Kernel 1: QKV GEMM + bias, fused per-head LayerNorm epilogue for Q,K,
//           scatter into head-major scratch.
// Tile: 64 (rows) x 64 (cols), K-chunk 16, 16x16 threads, 4x4 per thread.
// Column tiles align exactly with one head's 64-dim slice -> LN is local.
// ============================================================================
__global__ __launch_bounds__(256)
void qkv_ln_kernel(const float* __restrict__ X,      // [4096,1024]
                   const float* __restrict__ W,      // [1024,3072]
                   const float* __restrict__ bias,   // [3072]
                   const float* __restrict__ qg, const float* __restrict__ qb,
                   const float* __restrict__ kg, const float* __restrict__ kb)
{
    __shared__ float Ash[16][65];     // [k][m], padded
    __shared__ float Bs [16][64];     // [k][n]
    __shared__ float sOut[64][65];    // output staging, padded
    __shared__ float smu[64], srs[64];

    const int tx = threadIdx.x, ty = threadIdx.y;
    const int tid = ty*16 + tx;
    const int row0 = blockIdx.y * 64;
    const int col0 = blockIdx.x * 64;

    float acc[4][4] = {};

    const int ka = tid & 15;     // A: k index
    const int ma = tid >> 4;     // A: base row (rows ma, ma+16, ma+32, ma+48)
    const int nb = tid & 63;     // B: col index
    const int kb0 = tid >> 6;    // B: base k (k kb0, kb0+4, kb0+8, kb0+12)

    for (int kk = 0; kk < HID; kk += 16) {
        #pragma unroll
        for (int i = 0; i < 4; i++) {
            int m = ma + 16*i;
            Ash[ka][m] = X[(row0+m)*HID + kk + ka];
        }
        #pragma unroll
        for (int i = 0; i < 4; i++) {
            int k = kb0 + 4*i;
            Bs[k][nb] = W[(kk+k)*QKV_N + col0 + nb];
        }
        __syncthreads();
        #pragma unroll
        for (int k = 0; k < 16; k++) {
            float a[4], b[4];
            #pragma unroll
            for (int i = 0; i < 4; i++) a[i] = Ash[k][ty*4+i];
            #pragma unroll
            for (int j = 0; j < 4; j++) b[j] = Bs[k][tx*4+j];
            #pragma unroll
            for (int i = 0; i < 4; i++)
                #pragma unroll
                for (int j = 0; j < 4; j++)
                    acc[i][j] += a[i]*b[j];
        }
        __syncthreads();
    }

    // bias + stage to shared
    #pragma unroll
    for (int i = 0; i < 4; i++)
        #pragma unroll
        for (int j = 0; j < 4; j++) {
            int m = ty*4+i, n = tx*4+j;
            sOut[m][n] = acc[i][j] + bias[col0+n];
        }
    __syncthreads();

    const int part = blockIdx.x / 16;   // 0=q, 1=k, 2=v
    const int head = blockIdx.x & 15;

    if (part == 2) {
        // V: straight scatter, coalesced (consecutive tid -> consecutive d)
        for (int e = tid; e < 4096; e += 256) {
            int m = e >> 6, d = e & 63;
            int t = row0 + m;
            int b = t >> 11, s = t & 2047;
            g_v[((b*NHEADS + head)*SEQ + s)*HDIM + d] = sOut[m][d];
        }
    } else {
        // LayerNorm over the 64 columns (== head_dim) per row
        if (tid < 64) {
            float mu = 0.f;
            #pragma unroll
            for (int d = 0; d < 64; d++) mu += sOut[tid][d];
            mu *= (1.0f/64.0f);
            float var = 0.f;
            #pragma unroll
            for (int d = 0; d < 64; d++) { float df = sOut[tid][d]-mu; var += df*df; }
            var *= (1.0f/64.0f);
            smu[tid] = mu;
            srs[tid] = rsqrtf(var + LN_EPS);
        }
        __syncthreads();
        const float* g  = (part == 0) ? qg : kg;
        const float* be = (part == 0) ? qb : kb;
        float* dst      = (part == 0) ? g_q : g_k;
        for (int e = tid; e < 4096; e += 256) {
            int m = e >> 6, d = e & 63;
            int t = row0 + m;
            int b = t >> 11, s = t & 2047;
            float val = (sOut[m][d]-smu[m])*srs[m]*g[d] + be[d];
            dst[((b*NHEADS + head)*SEQ + s)*HDIM + d] = val;
        }
    }
}

// ============================================================================
// Kernel 2: causal flash attention, fp32.
// Grid: (32 q-tiles [reversed for load balance], 32 head-batches). 64 threads.
// Thread i owns q-row i of the tile: q[64], o[64] in registers.
// K/V tiles in SMEM [64][64] (conflict-free: write Ks[t][lane]), scores
// staged transposed in SMEM Sc[j][i] (conflict-free both directions).
// Inner products read K/V rows via broadcast LDS.128 (1 LDS / 4 FMA).
// ============================================================================
__global__ __launch_bounds__(64)
void attn_kernel()
{
    __shared__ float Ks[64][64];
    __shared__ float Vs[64][64];
    __shared__ float Sc[64][64];   // transposed: Sc[j][i]

    const int qt = (int)gridDim.x - 1 - (int)blockIdx.x;  // heavy blocks first
    const int bh = blockIdx.y;                            // b*NHEADS + h
    const int i  = threadIdx.x;                           // 0..63
    const int qrow = qt*64 + i;

    const float* qptr = &g_q[(bh*SEQ + qrow)*HDIM];
    float q[64], o[64];
    #pragma unroll
    for (int d = 0; d < 64; d++) { q[d] = qptr[d]; o[d] = 0.f; }
    float mM = -1e30f, l = 0.f;

    for (int kt = 0; kt <= qt; kt++) {
        // Load K/V tiles: iteration t, lane i -> coalesced global,
        // conflict-free shared (banks = lane).
        const float* kbase = &g_k[(bh*SEQ + kt*64)*HDIM];
        const float* vbase = &g_v[(bh*SEQ + kt*64)*HDIM];
        #pragma unroll 4
        for (int t = 0; t < 64; t++) {
            Ks[t][i] = kbase[t*HDIM + i];
            Vs[t][i] = vbase[t*HDIM + i];
        }
        __syncthreads();

        // Pass 1: scores for my row vs all 64 keys; track tile max.
        float tmax = -1e30f;
        const bool diag = (kt == qt);
        for (int j = 0; j < 64; j++) {
            float s0 = 0.f, s1 = 0.f, s2 = 0.f, s3 = 0.f;
            const float4* krow = (const float4*)&Ks[j][0];
            #pragma unroll
            for (int d4 = 0; d4 < 16; d4++) {
                float4 k4 = krow[d4];   // broadcast across lanes
                s0 += q[d4*4+0]*k4.x;
                s1 += q[d4*4+1]*k4.y;
                s2 += q[d4*4+2]*k4.z;
                s3 += q[d4*4+3]*k4.w;
            }
            float s = ((s0+s1)+(s2+s3)) * 0.125f;   // HD^-0.5
            if (diag && (kt*64 + j > qrow)) s = -1e30f;
            Sc[j][i] = s;
            tmax = fmaxf(tmax, s);
        }

        // Online softmax rescale
        float mNew = fmaxf(mM, tmax);
        float alpha = __expf(mM - mNew);
        l *= alpha;
        #pragma unroll
        for (int d = 0; d < 64; d++) o[d] *= alpha;

        // Pass 2: p = exp(s - mNew); accumulate PV.
        for (int j = 0; j < 64; j++) {
            float p = __expf(Sc[j][i] - mNew);
            l += p;
            const float4* vrow = (const float4*)&Vs[j][0];
            #pragma unroll
            for (int d4 = 0; d4 < 16; d4++) {
                float4 v4 = vrow[d4];   // broadcast
                o[d4*4+0] += p*v4.x;
                o[d4*4+1] += p*v4.y;
                o[d4*4+2] += p*v4.z;
                o[d4*4+3] += p*v4.w;
            }
        }
        mM = mNew;
        __syncthreads();
    }

    const float inv = 1.0f / l;
    const int b = bh >> 4, h = bh & 15;
    float* op = &g_ao[(b*SEQ + qrow)*HID + h*HDIM];
    #pragma unroll
    for (int d = 0; d < 64; d++) op[d] = o[d]*inv;
}

// ============================================================================
// Kernel 3: output projection  out = g_ao[4096,1024] @ W_proj[1024,1024] + b
// Same tiling as kernel 1, plain epilogue, coalesced store via staging.
// ============================================================================
__global__ __launch_bounds__(256)
void proj_kernel(const float* __restrict__ W,      // [1024,1024]
                 const float* __restrict__ bias,   // [1024]
                 float* __restrict__ out)          // [4096,1024]
{
    __shared__ float Ash[16][65];
    __shared__ float Bs [16][64];
    __shared__ float sOut[64][65];

    const int tx = threadIdx.x, ty = threadIdx.y;
    const int tid = ty*16 + tx;
    const int row0 = blockIdx.y * 64;
    const int col0 = blockIdx.x * 64;

    float acc[4][4] = {};

    const int ka = tid & 15;
    const int ma = tid >> 4;
    const int nb = tid & 63;
    const int kb0 = tid >> 6;

    for (int kk = 0; kk < HID; kk += 16) {
        #pragma unroll
        for (int i = 0; i < 4; i++) {
            int m = ma + 16*i;
            Ash[ka][m] = g_ao[(row0+m)*HID + kk + ka];
        }
        #pragma unroll
        for (int i = 0; i < 4; i++) {
            int k = kb0 + 4*i;
            Bs[k][nb] = W[(kk+k)*HID + col0 + nb];
        }
        __syncthreads();
        #pragma unroll
        for (int k = 0; k < 16; k++) {
            float a[4], b[4];
            #pragma unroll
            for (int i = 0; i < 4; i++) a[i] = Ash[k][ty*4+i];
            #pragma unroll
            for (int j = 0; j < 4; j++) b[j] = Bs[k][tx*4+j];
            #pragma unroll
            for (int i = 0; i < 4; i++)
                #pragma unroll
                for (int j = 0; j < 4; j++)
                    acc[i][j] += a[i]*b[j];
        }
        __syncthreads();
    }

    #pragma unroll
    for (int i = 0; i < 4; i++)
        #pragma unroll
        for (int j = 0; j < 4; j++) {
            int m = ty*4+i, n = tx*4+j;
            sOut[m][n] = acc[i][j] + bias[col0+n];
        }
    __syncthreads();

    for (int e = tid; e < 4096; e += 256) {
        int m = e >> 6, d = e & 63;
        out[(row0+m)*HID + col0 + d] = sOut[m][d];
    }
}

// ============================================================================
// launch
// ============================================================================
extern "C" void kernel_launch(void* const* d_in, const int* in_sizes, int n_in,
                              void* d_out, int out_size)
{
    const float* X      = (const float*)d_in[0];  // hidden_states [2,2048,1024]
    const float* W_attn = (const float*)d_in[1];  // [1024,3072]
    const float* b_attn = (const float*)d_in[2];  // [3072]
    const float* W_proj = (const float*)d_in[3];  // [1024,1024]
    const float* b_proj = (const float*)d_in[4];  // [1024]
    const float* qg     = (const float*)d_in[5];
    const float* qb     = (const float*)d_in[6];
    const float* kg     = (const float*)d_in[7];
    const float* kb     = (const float*)d_in[8];
    float* out = (float*)d_out;

    dim3 g1(QKV_N/64, MTOT/64);   // 48 x 64
    dim3 b16(16, 16);
    qkv_ln_kernel<<<g1, b16>>>(X, W_attn, b_attn, qg, qb, kg, kb);

    dim3 g2(SEQ/64, BATCH*NHEADS); // 32 x 32
    attn_kernel<<<g2, 64>>>();

    dim3 g3(HID/64, MTOT/64);     // 16 x 64
    proj_kernel<<<g3, b16>>>(W_proj, b_proj, out);
}